// round 15
// baseline (speedup 1.0000x reference)
#include <cuda_runtime.h>
#include <cuda_bf16.h>
#include <cuda_fp8.h>
#include <cstdint>
#include <math.h>

// NTXentLoss via mma.sync FP8 (e4m3) GEMM, symmetric upper-triangular tiles.
// Round 15: loss fused into simexp via per-row-block dependency counters --
// the CTA whose write completes block K computes K's loss partial right away
// (overlapped with other CTAs' MMA); 64th partial triggers the final reduce.
// Core = round 14 (best measured): fp8 tiles, 105 KB smem, 2 CTAs/SM.

#define M_TOTAL 8192
#define N_HALF  4096
#define DDIM    256
#define RT      128
#define NT64    (M_TOTAL / RT)           // 64 tile blocks
#define STRIP   4
#define SMS_B   272                      // fp8 tile row stride: 256 B + 16 pad
#define SQRT_L2E2 1.6986441f             // sqrt(2/ln2); dot = 2*log2e*sim

// Scratch (__device__ globals: allocation-free rule)
__device__ uint8_t g_Z[M_TOTAL * DDIM];             // normalized*s, e4m3
__device__ float g_pos[M_TOTAL];                    // 2*sim[i, pair] (fp32)
__device__ float g_spart[NT64][M_TOTAL];            // partial sums, slot-unique
__device__ float g_lpart[NT64];                     // per-block loss partials
__device__ unsigned int g_blk[NT64];                // per-block write counters
__device__ unsigned int g_fin;                      // finished-block counter

// smem layout (bytes) — total ~105 KB -> 2 CTAs/SM
#define SM_A    0
#define SM_B0   (RT * SMS_B)             // 34816
#define SM_B1   (2 * RT * SMS_B)         // 69632
#define SM_CSC  (3 * RT * SMS_B)         // 104448: csc[4][2][32] floats
#define SMEM_BYTES (SM_CSC + 4 * 2 * 32 * 4)   // 105472

// ---------------- PTX helpers (compute_103-safe subset) ----------------
__device__ __forceinline__ uint32_t smem_to_u32(const void* p) {
    uint32_t a;
    asm("{ .reg .u64 t; cvta.to.shared.u64 t, %1; cvt.u32.u64 %0, t; }"
        : "=r"(a) : "l"(p));
    return a;
}
__device__ __forceinline__ void ldsm4(uint32_t* r, uint32_t addr) {
    asm volatile("ldmatrix.sync.aligned.m8n8.x4.shared.b16 {%0,%1,%2,%3}, [%4];"
                 : "=r"(r[0]), "=r"(r[1]), "=r"(r[2]), "=r"(r[3]) : "r"(addr));
}
__device__ __forceinline__ void mma16832(float* d, const uint32_t* a, const uint32_t* b) {
    asm volatile(
        "mma.sync.aligned.m16n8k32.row.col.f32.e4m3.e4m3.f32 "
        "{%0,%1,%2,%3}, {%4,%5,%6,%7}, {%8,%9}, {%0,%1,%2,%3};"
        : "+f"(d[0]), "+f"(d[1]), "+f"(d[2]), "+f"(d[3])
        : "r"(a[0]), "r"(a[1]), "r"(a[2]), "r"(a[3]), "r"(b[0]), "r"(b[1]));
}
__device__ __forceinline__ void cp16(uint32_t smaddr, const void* gptr) {
    asm volatile("cp.async.cg.shared.global [%0], [%1], 16;"
                 :: "r"(smaddr), "l"(gptr) : "memory");
}
#define CP_COMMIT() asm volatile("cp.async.commit_group;" ::: "memory")
template <int N>
__device__ __forceinline__ void cp_wait() {
    asm volatile("cp.async.wait_group %0;" :: "n"(N) : "memory");
}
__device__ __forceinline__ void barpair(int id) {    // 2-warp named barrier
    asm volatile("bar.sync %0, 64;" :: "r"(id) : "memory");
}
__device__ __forceinline__ float ex2(float x) {
    float r;
    asm("ex2.approx.f32 %0, %1;" : "=f"(r) : "f"(x));
    return r;
}

// Async-copy one 128x256-byte fp8 tile into smem (2048 16B chunks, 256 thr).
__device__ __forceinline__ void cp_tile(uint32_t smb, int smoff, int row0) {
    const int tid = threadIdx.x;
    #pragma unroll
    for (int it = 0; it < 8; ++it) {
        int idx = it * 256 + tid;
        int r = idx >> 4;
        int c = idx & 15;
        cp16(smb + smoff + r * SMS_B + c * 16,
             g_Z + (size_t)(row0 + r) * DDIM + c * 16);
    }
}

// ---------------------------------------------------------------------------
// Kernel A: normalize, scale by sqrt(2*log2e), e4m3 quantize; fused pos dot.
// Two pairs per warp (ILP). Also resets the fused-loss counters.
// ---------------------------------------------------------------------------
__global__ __launch_bounds__(256) void norm_kernel(const float* __restrict__ zis,
                                                   const float* __restrict__ zjs)
{
    if (blockIdx.x == 0) {
        if (threadIdx.x < NT64) g_blk[threadIdx.x] = 0u;
        else if (threadIdx.x == NT64) g_fin = 0u;
    }

    const int wid = threadIdx.x >> 5, lane = threadIdx.x & 31;
    const int ibase = blockIdx.x * 16 + wid * 2;        // 256 blocks x 8 warps x 2
    #pragma unroll
    for (int u = 0; u < 2; ++u) {
        const int i = ibase + u;
        const float* sj = zjs + (size_t)i * DDIM;
        const float* si = zis + (size_t)i * DDIM;

        float4 j0 = reinterpret_cast<const float4*>(sj)[lane];
        float4 j1 = reinterpret_cast<const float4*>(sj)[lane + 32];
        float4 i0 = reinterpret_cast<const float4*>(si)[lane];
        float4 i1 = reinterpret_cast<const float4*>(si)[lane + 32];

        float ssj = j0.x*j0.x + j0.y*j0.y + j0.z*j0.z + j0.w*j0.w
                  + j1.x*j1.x + j1.y*j1.y + j1.z*j1.z + j1.w*j1.w;
        float ssi = i0.x*i0.x + i0.y*i0.y + i0.z*i0.z + i0.w*i0.w
                  + i1.x*i1.x + i1.y*i1.y + i1.z*i1.z + i1.w*i1.w;
        float dot = j0.x*i0.x + j0.y*i0.y + j0.z*i0.z + j0.w*i0.w
                  + j1.x*i1.x + j1.y*i1.y + j1.z*i1.z + j1.w*i1.w;
        #pragma unroll
        for (int o = 16; o > 0; o >>= 1) {
            ssj += __shfl_xor_sync(0xffffffffu, ssj, o);
            ssi += __shfl_xor_sync(0xffffffffu, ssi, o);
            dot += __shfl_xor_sync(0xffffffffu, dot, o);
        }
        float invj = 1.0f / fmaxf(sqrtf(ssj), 1e-8f);
        float invi = 1.0f / fmaxf(sqrtf(ssi), 1e-8f);
        if (lane == 0) {
            float p = 2.0f * dot * invi * invj;
            g_pos[i] = p;
            g_pos[i + N_HALF] = p;
        }
        const float qj = invj * SQRT_L2E2;
        const float qi = invi * SQRT_L2E2;
        uint32_t* dj = reinterpret_cast<uint32_t*>(g_Z + (size_t)i * DDIM);
        uint32_t* di = reinterpret_cast<uint32_t*>(g_Z + (size_t)(i + N_HALF) * DDIM);
        __nv_fp8x4_e4m3 pj0(make_float4(j0.x*qj, j0.y*qj, j0.z*qj, j0.w*qj));
        __nv_fp8x4_e4m3 pj1(make_float4(j1.x*qj, j1.y*qj, j1.z*qj, j1.w*qj));
        __nv_fp8x4_e4m3 pi0(make_float4(i0.x*qi, i0.y*qi, i0.z*qi, i0.w*qi));
        __nv_fp8x4_e4m3 pi1(make_float4(i1.x*qi, i1.y*qi, i1.z*qi, i1.w*qi));
        dj[lane]      = *reinterpret_cast<uint32_t*>(&pj0);
        dj[lane + 32] = *reinterpret_cast<uint32_t*>(&pj1);
        di[lane]      = *reinterpret_cast<uint32_t*>(&pi0);
        di[lane + 32] = *reinterpret_cast<uint32_t*>(&pi1);
    }
}

// ---------------------------------------------------------------------------
// Kernel B: strip of up to 4 upper-tri tiles per CTA + fused loss tail.
// Static grid (16, 64); J0 = I + 4x (early exit if J0 >= 64).
// 256 threads, warps 2(M) x 4(N), warp tile 64x32, FP8 k-loop (8 x k=32).
// ---------------------------------------------------------------------------
__global__ __launch_bounds__(256, 2) void simexp_kernel(float* __restrict__ out)
{
    const int I = blockIdx.y;
    const int J0 = I + STRIP * blockIdx.x;
    if (J0 >= NT64) return;
    const int nt = min(STRIP, NT64 - J0);

    extern __shared__ char sm[];
    __shared__ int s_ready[STRIP + 1];
    __shared__ int s_nready;
    __shared__ float s_lred[4];
    __shared__ int s_last;
    const uint32_t smb = smem_to_u32(sm);
    const int tid = threadIdx.x;
    const int wid = tid >> 5;
    const int lane = tid & 31;
    const int wm = wid >> 2;              // 0..1 (M)
    const int wn = wid & 3;               // 0..3 (N)
    const int rb = I * RT;

    // fp8 ldmatrix addressing (b16 view; validated round 12):
    const int a_row  = wm * 64 + (lane & 7) + ((lane >> 3) & 1) * 8;
    const int a_kadB = (lane >> 4) * 16;
    const int b_row  = wn * 32 + (lane & 7) + ((lane >> 4) & 1) * 8;
    const int b_kadB = ((lane >> 3) & 1) * 16;

    const uint32_t smA = smb + SM_A;
    float* csc = reinterpret_cast<float*>(sm + SM_CSC);   // [4 wn][2 wm][32]

    // Prologue: A + (B of first tile, unless diagonal)
    cp_tile(smb, SM_A, rb);
    if (J0 != I) cp_tile(smb, SM_B0, J0 * RT);
    CP_COMMIT();

    const int qrow = lane >> 2;
    const int drow0 = rb + wm * 64 + qrow;

    float rsum[8];                          // strip-persistent row sums
    #pragma unroll
    for (int q = 0; q < 8; ++q) rsum[q] = 0.f;

    int buf = 0;
    for (int s = 0; s < nt; ++s) {
        const int J = J0 + s;
        const int cb = J * RT;
        const bool diagT = (J == I);

        cp_wait<0>();
        __syncthreads();                    // single CTA sync per tile

        if (s + 1 < nt) {
            cp_tile(smb, (buf ^ 1) ? SM_B1 : SM_B0, (J + 1) * RT);
            CP_COMMIT();
        }

        const uint32_t smB = diagT ? smA : (smb + (buf ? SM_B1 : SM_B0));

        float d[4][4][4];
        #pragma unroll
        for (int mf = 0; mf < 4; ++mf)
            #pragma unroll
            for (int nf = 0; nf < 4; ++nf)
                #pragma unroll
                for (int e = 0; e < 4; ++e) d[mf][nf][e] = 0.f;

        #pragma unroll
        for (int ks = 0; ks < DDIM / 32; ++ks) {
            const int k0b = ks * 32;
            uint32_t a[4][4];
            #pragma unroll
            for (int mf = 0; mf < 4; ++mf)
                ldsm4(a[mf], smA + (uint32_t)(a_row + mf * 16) * SMS_B
                                 + (uint32_t)(k0b + a_kadB));
            #pragma unroll
            for (int nh = 0; nh < 2; ++nh) {
                uint32_t r4[4];
                ldsm4(r4, smB + (uint32_t)(b_row + nh * 16) * SMS_B
                              + (uint32_t)(k0b + b_kadB));
                uint32_t b0[2] = {r4[0], r4[1]};
                uint32_t b1[2] = {r4[2], r4[3]};
                #pragma unroll
                for (int mf = 0; mf < 4; ++mf) {
                    mma16832(d[mf][2*nh],     a[mf], b0);
                    mma16832(d[mf][2*nh + 1], a[mf], b1);
                }
            }
        }

        // Epilogue: e = ex2(d) = exp(2*sim) (scale folded into Z).
        const int dcol0 = cb + wn * 32 + 2 * (lane & 3);
        float csum[8];
        #pragma unroll
        for (int q = 0; q < 8; ++q) csum[q] = 0.f;

        #pragma unroll
        for (int mf = 0; mf < 4; ++mf) {
            const int r0 = drow0 + mf * 16;
            #pragma unroll
            for (int nf = 0; nf < 4; ++nf) {
                const int c0 = dcol0 + nf * 8;
                float e0 = ex2(d[mf][nf][0]);
                float e1 = ex2(d[mf][nf][1]);
                float e2 = ex2(d[mf][nf][2]);
                float e3 = ex2(d[mf][nf][3]);
                if (diagT) {
                    if (c0     == r0    ) e0 = 0.f;
                    if (c0 + 1 == r0    ) e1 = 0.f;
                    if (c0     == r0 + 8) e2 = 0.f;
                    if (c0 + 1 == r0 + 8) e3 = 0.f;
                }
                rsum[mf*2]   += e0 + e1;
                rsum[mf*2+1] += e2 + e3;
                csum[nf*2]   += e0 + e2;
                csum[nf*2+1] += e1 + e3;
            }
        }

        if (!diagT) {
            #pragma unroll
            for (int q = 0; q < 8; ++q) {
                float w = csum[q];
                w += __shfl_xor_sync(0xffffffffu, w, 4);
                w += __shfl_xor_sync(0xffffffffu, w, 8);
                w += __shfl_xor_sync(0xffffffffu, w, 16);
                csum[q] = w;
            }
            float* my = csc + (wn * 2 + wm) * 32;
            if (lane < 4) {
                #pragma unroll
                for (int nf = 0; nf < 4; ++nf)
                    #pragma unroll
                    for (int e2 = 0; e2 < 2; ++e2)
                        my[nf * 8 + 2 * lane + e2] = csum[nf*2+e2];
            }
            barpair(1 + wn);
            if (wm == 1) {
                float v = csc[(wn*2+0)*32 + lane] + csc[(wn*2+1)*32 + lane];
                g_spart[I][cb + wn * 32 + lane] = v;
            }
        }

        if (s + 1 < nt) buf ^= 1;
    }

    // Strip end: reduce row sums (quad lanes share rows) and write slot J0.
    #pragma unroll
    for (int q = 0; q < 8; ++q) {
        float v = rsum[q];
        v += __shfl_xor_sync(0xffffffffu, v, 1);
        v += __shfl_xor_sync(0xffffffffu, v, 2);
        rsum[q] = v;
    }
    __syncthreads();                        // all mma reads of smA done
    float* redR = reinterpret_cast<float*>(sm);          // [4 wn][128]
    if ((lane & 3) == 0) {
        #pragma unroll
        for (int mf = 0; mf < 4; ++mf)
            #pragma unroll
            for (int h = 0; h < 2; ++h)
                redR[wn * RT + wm * 64 + mf * 16 + h * 8 + qrow] = rsum[mf*2+h];
    }
    __syncthreads();
    if (tid < RT) {
        float rs = redR[tid] + redR[RT+tid] + redR[2*RT+tid] + redR[3*RT+tid];
        g_spart[J0][rb + tid] = rs;
    }

    // ---- Fused loss: dependency-counted per-row-block completion ----
    // Block K is complete after expected(K) = ceil((64-K)/4) + K writes:
    // its own row-strips (slot J0 writes) + one col write per I < K.
    // This strip wrote: row-slot of block I, col-slots of blocks J != I.
    __threadfence();                        // ALL threads fence their g_spart writes
    __syncthreads();
    if (tid == 0) {
        int n = 0;
        #pragma unroll
        for (int q = 0; q < STRIP + 1; ++q) {
            int K;
            if (q == 0) K = I;
            else {
                int J = J0 + (q - 1);
                if (q - 1 >= nt || J == I) continue;
                K = J;
            }
            unsigned v = atomicAdd(&g_blk[K], 1u) + 1u;
            if (v == (unsigned)(((67 - K) >> 2) + K)) s_ready[n++] = K;
        }
        s_nready = n;
    }
    __syncthreads();

    const int nready = s_nready;
    for (int q = 0; q < nready; ++q) {
        const int K = s_ready[q];
        __threadfence();                    // acquire side
        float acc = 0.f;
        if (tid < RT) {
            const int i = K * RT + tid;
            float s = 0.f;
            #pragma unroll 8
            for (int t = 0; t < NT64; ++t)
                s += g_spart[t][i];
            acc = __logf(s) - g_pos[i];
        }
        #pragma unroll
        for (int o = 16; o > 0; o >>= 1)
            acc += __shfl_xor_sync(0xffffffffu, acc, o);
        if (tid < RT && lane == 0) s_lred[wid] = acc;
        __syncthreads();
        if (tid == 0) {
            float tot = s_lred[0] + s_lred[1] + s_lred[2] + s_lred[3];
            g_lpart[K] = tot;
            __threadfence();
            unsigned v = atomicAdd(&g_fin, 1u);
            s_last = (v == (unsigned)(NT64 - 1));
        }
        __syncthreads();
        if (s_last) {
            __threadfence();
            if (tid < 32) {
                float v = g_lpart[tid] + g_lpart[tid + 32];
                #pragma unroll
                for (int o = 16; o > 0; o >>= 1)
                    v += __shfl_xor_sync(0xffffffffu, v, o);
                if (tid == 0) out[0] = v / (float)M_TOTAL;
            }
        }
        __syncthreads();                    // s_lred reuse across q iterations
    }
}

// ---------------------------------------------------------------------------
extern "C" void kernel_launch(void* const* d_in, const int* in_sizes, int n_in,
                              void* d_out, int out_size)
{
    const float* zis = (const float*)d_in[0];
    const float* zjs = (const float*)d_in[1];
    float* out = (float*)d_out;

    norm_kernel<<<N_HALF / 16, 256>>>(zis, zjs);

    cudaFuncSetAttribute(simexp_kernel,
                         cudaFuncAttributeMaxDynamicSharedMemorySize, SMEM_BYTES);
    simexp_kernel<<<dim3(16, NT64), 256, SMEM_BYTES>>>(out);
}

// round 16
// speedup vs baseline: 1.2587x; 1.2587x over previous
#include <cuda_runtime.h>
#include <cuda_bf16.h>
#include <cuda_fp8.h>
#include <cstdint>
#include <math.h>

// NTXentLoss via mma.sync FP8 (e4m3) GEMM, symmetric upper-triangular tiles.
// Round 16: round-14 core (best measured: fp8 tiles, 105 KB smem, 2 CTAs/SM,
// 256 thr, 2x4 warps) with STRIP=8 -> 288 strips run in ONE wave (296 slots):
// halved prologues/strip-end overheads, no wave-transition. Separate tiny
// loss kernel (threadfence reduction) — the fused tail of R15 regressed.

#define M_TOTAL 8192
#define N_HALF  4096
#define DDIM    256
#define RT      128
#define NT64    (M_TOTAL / RT)           // 64 tile blocks
#define STRIP   8
#define SMS_B   272                      // fp8 tile row stride: 256 B + 16 pad
#define SQRT_L2E2 1.6986441f             // sqrt(2/ln2); dot = 2*log2e*sim

// Scratch (__device__ globals: allocation-free rule)
__device__ uint8_t g_Z[M_TOTAL * DDIM];             // normalized*s, e4m3
__device__ float g_pos[M_TOTAL];                    // 2*sim[i, pair] (fp32)
__device__ float g_spart[NT64][M_TOTAL];            // partial sums, slot-unique
__device__ float g_red[32];                         // loss block partials
__device__ unsigned int g_ctr;                      // loss completion counter

// smem layout (bytes) — total ~105 KB -> 2 CTAs/SM
#define SM_A    0
#define SM_B0   (RT * SMS_B)             // 34816
#define SM_B1   (2 * RT * SMS_B)         // 69632
#define SM_CSC  (3 * RT * SMS_B)         // 104448: csc[4][2][32] floats
#define SMEM_BYTES (SM_CSC + 4 * 2 * 32 * 4)   // 105472

// ---------------- PTX helpers (compute_103-safe subset) ----------------
__device__ __forceinline__ uint32_t smem_to_u32(const void* p) {
    uint32_t a;
    asm("{ .reg .u64 t; cvta.to.shared.u64 t, %1; cvt.u32.u64 %0, t; }"
        : "=r"(a) : "l"(p));
    return a;
}
__device__ __forceinline__ void ldsm4(uint32_t* r, uint32_t addr) {
    asm volatile("ldmatrix.sync.aligned.m8n8.x4.shared.b16 {%0,%1,%2,%3}, [%4];"
                 : "=r"(r[0]), "=r"(r[1]), "=r"(r[2]), "=r"(r[3]) : "r"(addr));
}
__device__ __forceinline__ void mma16832(float* d, const uint32_t* a, const uint32_t* b) {
    asm volatile(
        "mma.sync.aligned.m16n8k32.row.col.f32.e4m3.e4m3.f32 "
        "{%0,%1,%2,%3}, {%4,%5,%6,%7}, {%8,%9}, {%0,%1,%2,%3};"
        : "+f"(d[0]), "+f"(d[1]), "+f"(d[2]), "+f"(d[3])
        : "r"(a[0]), "r"(a[1]), "r"(a[2]), "r"(a[3]), "r"(b[0]), "r"(b[1]));
}
__device__ __forceinline__ void cp16(uint32_t smaddr, const void* gptr) {
    asm volatile("cp.async.cg.shared.global [%0], [%1], 16;"
                 :: "r"(smaddr), "l"(gptr) : "memory");
}
#define CP_COMMIT() asm volatile("cp.async.commit_group;" ::: "memory")
template <int N>
__device__ __forceinline__ void cp_wait() {
    asm volatile("cp.async.wait_group %0;" :: "n"(N) : "memory");
}
__device__ __forceinline__ void barpair(int id) {    // 2-warp named barrier
    asm volatile("bar.sync %0, 64;" :: "r"(id) : "memory");
}
__device__ __forceinline__ float ex2(float x) {
    float r;
    asm("ex2.approx.f32 %0, %1;" : "=f"(r) : "f"(x));
    return r;
}

// Async-copy one 128x256-byte fp8 tile into smem (2048 16B chunks, 256 thr).
__device__ __forceinline__ void cp_tile(uint32_t smb, int smoff, int row0) {
    const int tid = threadIdx.x;
    #pragma unroll
    for (int it = 0; it < 8; ++it) {
        int idx = it * 256 + tid;
        int r = idx >> 4;
        int c = idx & 15;
        cp16(smb + smoff + r * SMS_B + c * 16,
             g_Z + (size_t)(row0 + r) * DDIM + c * 16);
    }
}

// ---------------------------------------------------------------------------
// Kernel A: normalize, scale by sqrt(2*log2e), e4m3 quantize; fused pos dot.
// Two pairs per warp (ILP). pos from raw fp32 (exact).
// ---------------------------------------------------------------------------
__global__ __launch_bounds__(256) void norm_kernel(const float* __restrict__ zis,
                                                   const float* __restrict__ zjs)
{
    const int wid = threadIdx.x >> 5, lane = threadIdx.x & 31;
    const int ibase = blockIdx.x * 16 + wid * 2;        // 256 blocks x 8 warps x 2
    #pragma unroll
    for (int u = 0; u < 2; ++u) {
        const int i = ibase + u;
        const float* sj = zjs + (size_t)i * DDIM;
        const float* si = zis + (size_t)i * DDIM;

        float4 j0 = reinterpret_cast<const float4*>(sj)[lane];
        float4 j1 = reinterpret_cast<const float4*>(sj)[lane + 32];
        float4 i0 = reinterpret_cast<const float4*>(si)[lane];
        float4 i1 = reinterpret_cast<const float4*>(si)[lane + 32];

        float ssj = j0.x*j0.x + j0.y*j0.y + j0.z*j0.z + j0.w*j0.w
                  + j1.x*j1.x + j1.y*j1.y + j1.z*j1.z + j1.w*j1.w;
        float ssi = i0.x*i0.x + i0.y*i0.y + i0.z*i0.z + i0.w*i0.w
                  + i1.x*i1.x + i1.y*i1.y + i1.z*i1.z + i1.w*i1.w;
        float dot = j0.x*i0.x + j0.y*i0.y + j0.z*i0.z + j0.w*i0.w
                  + j1.x*i1.x + j1.y*i1.y + j1.z*i1.z + j1.w*i1.w;
        #pragma unroll
        for (int o = 16; o > 0; o >>= 1) {
            ssj += __shfl_xor_sync(0xffffffffu, ssj, o);
            ssi += __shfl_xor_sync(0xffffffffu, ssi, o);
            dot += __shfl_xor_sync(0xffffffffu, dot, o);
        }
        float invj = 1.0f / fmaxf(sqrtf(ssj), 1e-8f);
        float invi = 1.0f / fmaxf(sqrtf(ssi), 1e-8f);
        if (lane == 0) {
            float p = 2.0f * dot * invi * invj;
            g_pos[i] = p;
            g_pos[i + N_HALF] = p;
        }
        const float qj = invj * SQRT_L2E2;
        const float qi = invi * SQRT_L2E2;
        uint32_t* dj = reinterpret_cast<uint32_t*>(g_Z + (size_t)i * DDIM);
        uint32_t* di = reinterpret_cast<uint32_t*>(g_Z + (size_t)(i + N_HALF) * DDIM);
        __nv_fp8x4_e4m3 pj0(make_float4(j0.x*qj, j0.y*qj, j0.z*qj, j0.w*qj));
        __nv_fp8x4_e4m3 pj1(make_float4(j1.x*qj, j1.y*qj, j1.z*qj, j1.w*qj));
        __nv_fp8x4_e4m3 pi0(make_float4(i0.x*qi, i0.y*qi, i0.z*qi, i0.w*qi));
        __nv_fp8x4_e4m3 pi1(make_float4(i1.x*qi, i1.y*qi, i1.z*qi, i1.w*qi));
        dj[lane]      = *reinterpret_cast<uint32_t*>(&pj0);
        dj[lane + 32] = *reinterpret_cast<uint32_t*>(&pj1);
        di[lane]      = *reinterpret_cast<uint32_t*>(&pi0);
        di[lane + 32] = *reinterpret_cast<uint32_t*>(&pi1);
    }
}

// ---------------------------------------------------------------------------
// Kernel B: strip of up to 8 upper-tri tiles per CTA. Static grid (8, 64):
// x = strip chunk, y = I; J0 = I + 8x (early exit if J0 >= 64). 288 active
// CTAs -> ONE wave at 2 CTAs/SM. 256 threads, warps 2(M) x 4(N), warp tile
// 64x32, FP8 k-loop (8 x k=32). __launch_bounds__(256, 2) caps regs at 128.
// ---------------------------------------------------------------------------
__global__ __launch_bounds__(256, 2) void simexp_kernel()
{
    const int I = blockIdx.y;
    const int J0 = I + STRIP * blockIdx.x;
    if (J0 >= NT64) return;
    const int nt = min(STRIP, NT64 - J0);

    extern __shared__ char sm[];
    const uint32_t smb = smem_to_u32(sm);
    const int tid = threadIdx.x;
    const int wid = tid >> 5;
    const int lane = tid & 31;
    const int wm = wid >> 2;              // 0..1 (M)
    const int wn = wid & 3;               // 0..3 (N)
    const int rb = I * RT;

    // fp8 ldmatrix addressing (b16 view; validated round 12):
    const int a_row  = wm * 64 + (lane & 7) + ((lane >> 3) & 1) * 8;
    const int a_kadB = (lane >> 4) * 16;
    const int b_row  = wn * 32 + (lane & 7) + ((lane >> 4) & 1) * 8;
    const int b_kadB = ((lane >> 3) & 1) * 16;

    const uint32_t smA = smb + SM_A;
    float* csc = reinterpret_cast<float*>(sm + SM_CSC);   // [4 wn][2 wm][32]

    // Prologue: A + (B of first tile, unless diagonal)
    cp_tile(smb, SM_A, rb);
    if (J0 != I) cp_tile(smb, SM_B0, J0 * RT);
    CP_COMMIT();

    const int qrow = lane >> 2;
    const int drow0 = rb + wm * 64 + qrow;

    float rsum[8];                          // strip-persistent row sums
    #pragma unroll
    for (int q = 0; q < 8; ++q) rsum[q] = 0.f;

    int buf = 0;
    for (int s = 0; s < nt; ++s) {
        const int J = J0 + s;
        const int cb = J * RT;
        const bool diagT = (J == I);

        cp_wait<0>();
        __syncthreads();                    // single CTA sync per tile

        if (s + 1 < nt) {
            cp_tile(smb, (buf ^ 1) ? SM_B1 : SM_B0, (J + 1) * RT);
            CP_COMMIT();
        }

        const uint32_t smB = diagT ? smA : (smb + (buf ? SM_B1 : SM_B0));

        float d[4][4][4];
        #pragma unroll
        for (int mf = 0; mf < 4; ++mf)
            #pragma unroll
            for (int nf = 0; nf < 4; ++nf)
                #pragma unroll
                for (int e = 0; e < 4; ++e) d[mf][nf][e] = 0.f;

        #pragma unroll
        for (int ks = 0; ks < DDIM / 32; ++ks) {
            const int k0b = ks * 32;        // byte offset of this k-chunk
            uint32_t a[4][4];
            #pragma unroll
            for (int mf = 0; mf < 4; ++mf)
                ldsm4(a[mf], smA + (uint32_t)(a_row + mf * 16) * SMS_B
                                 + (uint32_t)(k0b + a_kadB));
            #pragma unroll
            for (int nh = 0; nh < 2; ++nh) {
                uint32_t r4[4];
                ldsm4(r4, smB + (uint32_t)(b_row + nh * 16) * SMS_B
                              + (uint32_t)(k0b + b_kadB));
                #pragma unroll
                for (int mf = 0; mf < 4; ++mf) {
                    mma16832(d[mf][2*nh],     a[mf], r4);
                    mma16832(d[mf][2*nh + 1], a[mf], r4 + 2);
                }
            }
        }

        // Epilogue: e = ex2(d) = exp(2*sim) (scale folded into Z).
        const int dcol0 = cb + wn * 32 + 2 * (lane & 3);
        float csum[8];
        #pragma unroll
        for (int q = 0; q < 8; ++q) csum[q] = 0.f;

        #pragma unroll
        for (int mf = 0; mf < 4; ++mf) {
            const int r0 = drow0 + mf * 16;
            #pragma unroll
            for (int nf = 0; nf < 4; ++nf) {
                const int c0 = dcol0 + nf * 8;
                float e0 = ex2(d[mf][nf][0]);
                float e1 = ex2(d[mf][nf][1]);
                float e2 = ex2(d[mf][nf][2]);
                float e3 = ex2(d[mf][nf][3]);
                if (diagT) {
                    if (c0     == r0    ) e0 = 0.f;
                    if (c0 + 1 == r0    ) e1 = 0.f;
                    if (c0     == r0 + 8) e2 = 0.f;
                    if (c0 + 1 == r0 + 8) e3 = 0.f;
                }
                rsum[mf*2]   += e0 + e1;
                rsum[mf*2+1] += e2 + e3;
                csum[nf*2]   += e0 + e2;
                csum[nf*2+1] += e1 + e3;
            }
        }

        if (!diagT) {
            #pragma unroll
            for (int q = 0; q < 8; ++q) {
                float w = csum[q];
                w += __shfl_xor_sync(0xffffffffu, w, 4);
                w += __shfl_xor_sync(0xffffffffu, w, 8);
                w += __shfl_xor_sync(0xffffffffu, w, 16);
                csum[q] = w;
            }
            float* my = csc + (wn * 2 + wm) * 32;
            if (lane < 4) {
                #pragma unroll
                for (int nf = 0; nf < 4; ++nf)
                    #pragma unroll
                    for (int e2 = 0; e2 < 2; ++e2)
                        my[nf * 8 + 2 * lane + e2] = csum[nf*2+e2];
            }
            barpair(1 + wn);
            if (wm == 1) {
                float v = csc[(wn*2+0)*32 + lane] + csc[(wn*2+1)*32 + lane];
                g_spart[I][cb + wn * 32 + lane] = v;
            }
        }

        if (s + 1 < nt) buf ^= 1;
    }

    // Strip end: reduce row sums (quad lanes share rows) and write slot J0.
    #pragma unroll
    for (int q = 0; q < 8; ++q) {
        float v = rsum[q];
        v += __shfl_xor_sync(0xffffffffu, v, 1);
        v += __shfl_xor_sync(0xffffffffu, v, 2);
        rsum[q] = v;
    }
    __syncthreads();                        // all mma reads of smA done
    float* redR = reinterpret_cast<float*>(sm);          // [4 wn][128]
    if ((lane & 3) == 0) {
        #pragma unroll
        for (int mf = 0; mf < 4; ++mf)
            #pragma unroll
            for (int h = 0; h < 2; ++h)
                redR[wn * RT + wm * 64 + mf * 16 + h * 8 + qrow] = rsum[mf*2+h];
    }
    __syncthreads();
    if (tid < RT) {
        float rs = redR[tid] + redR[RT+tid] + redR[2*RT+tid] + redR[3*RT+tid];
        g_spart[J0][rb + tid] = rs;
    }
}

// ---------------------------------------------------------------------------
// Kernel D: merged loss (threadfence reduction; deterministic).
// ---------------------------------------------------------------------------
__global__ __launch_bounds__(256) void loss_kernel(float* __restrict__ out)
{
    __shared__ float red[8];
    __shared__ bool amLast;
    const int tid = threadIdx.x;
    const int i = blockIdx.x * 256 + tid;       // exactly 8192 threads
    float s = 0.f;
    #pragma unroll 8
    for (int t = 0; t < NT64; ++t)
        s += g_spart[t][i];
    float acc = __logf(s) - g_pos[i];
    #pragma unroll
    for (int o = 16; o > 0; o >>= 1)
        acc += __shfl_xor_sync(0xffffffffu, acc, o);
    if ((tid & 31) == 0) red[tid >> 5] = acc;
    __syncthreads();
    if (tid == 0) {
        float t = 0.f;
        #pragma unroll
        for (int w = 0; w < 8; ++w) t += red[w];
        g_red[blockIdx.x] = t;
        __threadfence();
        unsigned int v = atomicAdd(&g_ctr, 1u);
        amLast = (v == 31u);
    }
    __syncthreads();
    if (amLast && tid < 32) {
        float v = g_red[tid];
        #pragma unroll
        for (int o = 16; o > 0; o >>= 1)
            v += __shfl_xor_sync(0xffffffffu, v, o);
        if (tid == 0) {
            out[0] = v / (float)M_TOTAL;
            g_ctr = 0u;                     // reset for next graph replay
        }
    }
}

// ---------------------------------------------------------------------------
extern "C" void kernel_launch(void* const* d_in, const int* in_sizes, int n_in,
                              void* d_out, int out_size)
{
    const float* zis = (const float*)d_in[0];
    const float* zjs = (const float*)d_in[1];
    float* out = (float*)d_out;

    norm_kernel<<<N_HALF / 16, 256>>>(zis, zjs);

    cudaFuncSetAttribute(simexp_kernel,
                         cudaFuncAttributeMaxDynamicSharedMemorySize, SMEM_BYTES);
    simexp_kernel<<<dim3(8, NT64), 256, SMEM_BYTES>>>();

    loss_kernel<<<32, 256>>>(out);
}